// round 1
// baseline (speedup 1.0000x reference)
#include <cuda_runtime.h>
#include <cstdint>

#define BB 8
#define SS 2048
#define DD 512
#define UU 512
#define L0 128
#define L1 128
#define QT 32            // queries per tile
#define NT (SS/QT)       // 64 tiles
#define WIN 288          // key window span per 32-query tile: 32 + 256
#define SCALE 0.044194173824159216f  // 1/sqrt(512)

// Scratch (static device globals — no allocation in kernel_launch)
__device__ float g_qkv[3ull * BB * SS * UU];   // q,k,v  (~100 MB)
__device__ float g_p[(size_t)BB * SS * WIN];   // softmax probs (~19 MB)

// ---------------------------------------------------------------------------
// Kernel 1: QKV projection GEMM.  C[16384,512] = X @ W + bias, z selects W.
// 128x128 tile, BK=8, 8x8 per thread, 256 threads.
// ---------------------------------------------------------------------------
__global__ __launch_bounds__(256) void qkv_gemm(
    const float* __restrict__ x,
    const float* __restrict__ Wq, const float* __restrict__ Wk, const float* __restrict__ Wv,
    const float* __restrict__ bq, const float* __restrict__ bk, const float* __restrict__ bv)
{
    const int w = blockIdx.z;
    const float* __restrict__ W    = (w == 0) ? Wq : (w == 1) ? Wk : Wv;
    const float* __restrict__ bias = (w == 0) ? bq : (w == 1) ? bk : bv;
    float* __restrict__ out = g_qkv + (size_t)w * BB * SS * UU;

    __shared__ float As[8][128];   // transposed A tile
    __shared__ float Bs[8][128];

    const int tid = threadIdx.x;
    const int m0 = blockIdx.y * 128;
    const int n0 = blockIdx.x * 128;
    const int tx = tid & 15;       // 16 col groups
    const int ty = tid >> 4;       // 16 row groups

    // A load mapping: row = tid/2, col4 = (tid%2)*4
    const int arow = tid >> 1;
    const int acol = (tid & 1) * 4;
    // B load mapping: row = tid/32, col4 = (tid%32)*4
    const int brow = tid >> 5;
    const int bcol = (tid & 31) * 4;

    float acc[8][8];
#pragma unroll
    for (int i = 0; i < 8; i++)
#pragma unroll
        for (int j = 0; j < 8; j++) acc[i][j] = 0.f;

    for (int k0 = 0; k0 < DD; k0 += 8) {
        float4 av = *(const float4*)&x[(size_t)(m0 + arow) * DD + k0 + acol];
        As[acol + 0][arow] = av.x;
        As[acol + 1][arow] = av.y;
        As[acol + 2][arow] = av.z;
        As[acol + 3][arow] = av.w;
        float4 bv4 = *(const float4*)&W[(size_t)(k0 + brow) * UU + n0 + bcol];
        *(float4*)&Bs[brow][bcol] = bv4;
        __syncthreads();

#pragma unroll
        for (int k = 0; k < 8; k++) {
            float a[8], b[8];
            *(float4*)&a[0] = *(const float4*)&As[k][ty * 8];
            *(float4*)&a[4] = *(const float4*)&As[k][ty * 8 + 4];
            *(float4*)&b[0] = *(const float4*)&Bs[k][tx * 8];
            *(float4*)&b[4] = *(const float4*)&Bs[k][tx * 8 + 4];
#pragma unroll
            for (int i = 0; i < 8; i++)
#pragma unroll
                for (int j = 0; j < 8; j++) acc[i][j] += a[i] * b[j];
        }
        __syncthreads();
    }

#pragma unroll
    for (int i = 0; i < 8; i++) {
        const size_t row = (size_t)(m0 + ty * 8 + i) * UU;
#pragma unroll
        for (int j = 0; j < 8; j++) {
            const int n = n0 + tx * 8 + j;
            out[row + n] = acc[i][j] + bias[n];
        }
    }
}

// ---------------------------------------------------------------------------
// Kernel 2: windowed scores + masked softmax for a 32-query tile.
// CTA = (q-tile, batch). Dynamic smem: Q[32][516] + K[32][65] + S[32][288].
// ---------------------------------------------------------------------------
#define QSTR 516
#define KSTR 65
#define SMEM_SC ((32*QSTR + 32*KSTR + 32*WIN) * 4)

__global__ __launch_bounds__(256) void scores_kernel()
{
    extern __shared__ float sm[];
    float* Qs = sm;                    // 32 x 516
    float* Ks = Qs + 32 * QSTR;        // 32 x 65
    float* Sx = Ks + 32 * KSTR;        // 32 x 288

    const int tid = threadIdx.x;
    const int b   = blockIdx.y;
    const int q0  = blockIdx.x * QT;
    const int kstart = q0 - L0;

    const float* __restrict__ gq = g_qkv + (size_t)(b * SS + q0) * UU;
    const float* __restrict__ gk = g_qkv + (size_t)BB * SS * UU + (size_t)b * SS * UU;

    // Load full Q tile (32x512) once
    for (int f = tid; f < 32 * 128; f += 256) {       // float4 units
        const int row = f >> 7, c4 = f & 127;
        float4 v = *(const float4*)&gq[(size_t)row * UU + c4 * 4];
        *(float4*)&Qs[row * QSTR + c4 * 4] = v;
    }
    __syncthreads();

    const int ty = tid >> 4;  // 0..15 -> queries 2ty, 2ty+1
    const int tx = tid & 15;  // 0..15 -> local keys 2tx, 2tx+1

    for (int kc = 0; kc < WIN / 32; kc++) {
        float a00 = 0.f, a01 = 0.f, a10 = 0.f, a11 = 0.f;
        const int kbase = kstart + kc * 32;

        for (int dc = 0; dc < DD; dc += 64) {
            // Load K chunk 32 x 64 (zero-fill OOB rows)
            for (int f = tid; f < 32 * 16; f += 256) { // float4 units
                const int row = f >> 4, c4 = f & 15;
                const int j = kbase + row;
                float4 v = make_float4(0.f, 0.f, 0.f, 0.f);
                if (j >= 0 && j < SS)
                    v = *(const float4*)&gk[(size_t)j * UU + dc + c4 * 4];
                float* p = &Ks[row * KSTR + c4 * 4];
                p[0] = v.x; p[1] = v.y; p[2] = v.z; p[3] = v.w;
            }
            __syncthreads();

            const float* q0p = &Qs[(2 * ty) * QSTR + dc];
            const float* q1p = &Qs[(2 * ty + 1) * QSTR + dc];
            const float* k0p = &Ks[(2 * tx) * KSTR];
            const float* k1p = &Ks[(2 * tx + 1) * KSTR];
#pragma unroll 16
            for (int d = 0; d < 64; d++) {
                const float qa = q0p[d], qb = q1p[d];
                const float ka = k0p[d], kb = k1p[d];
                a00 += qa * ka; a01 += qa * kb;
                a10 += qb * ka; a11 += qb * kb;
            }
            __syncthreads();
        }
        Sx[(2 * ty)     * WIN + kc * 32 + 2 * tx]     = a00 * SCALE;
        Sx[(2 * ty)     * WIN + kc * 32 + 2 * tx + 1] = a01 * SCALE;
        Sx[(2 * ty + 1) * WIN + kc * 32 + 2 * tx]     = a10 * SCALE;
        Sx[(2 * ty + 1) * WIN + kc * 32 + 2 * tx + 1] = a11 * SCALE;
    }
    __syncthreads();

    // Masked softmax: warp w handles rows w, w+8, w+16, w+24
    const int lane = tid & 31;
    for (int rr = tid >> 5; rr < QT; rr += 8) {
        const int i = q0 + rr;
        int cmin = rr;               // j >= i - L0  <=>  c >= rr
        if (-kstart > cmin) cmin = -kstart;          // j >= 0
        int cmax = rr + L0 + L1;     // j <= i + L1  <=>  c <= rr + 256
        const int chi = SS - 1 - kstart;             // j <= S-1
        if (chi < cmax) cmax = chi;

        float mx = -1e30f;
        for (int c = lane; c < WIN; c += 32)
            if (c >= cmin && c <= cmax) mx = fmaxf(mx, Sx[rr * WIN + c]);
#pragma unroll
        for (int off = 16; off > 0; off >>= 1)
            mx = fmaxf(mx, __shfl_xor_sync(0xFFFFFFFFu, mx, off));

        float sum = 0.f;
        for (int c = lane; c < WIN; c += 32) {
            float e = 0.f;
            if (c >= cmin && c <= cmax) e = __expf(Sx[rr * WIN + c] - mx);
            Sx[rr * WIN + c] = e;
            sum += e;
        }
#pragma unroll
        for (int off = 16; off > 0; off >>= 1)
            sum += __shfl_xor_sync(0xFFFFFFFFu, sum, off);

        const float inv = 1.0f / sum;
        float* __restrict__ prow = &g_p[((size_t)b * SS + i) * WIN];
        for (int c = lane; c < WIN; c += 32)
            prow[c] = Sx[rr * WIN + c] * inv;
    }
}

// ---------------------------------------------------------------------------
// Kernel 3: out = P @ V over the 288-key window.
// CTA = (dv-chunk 128, q-tile, batch). 256 threads, 4x4 per thread.
// ---------------------------------------------------------------------------
__global__ __launch_bounds__(256) void av_kernel(float* __restrict__ out)
{
    __shared__ float Ps[32][32];
    __shared__ float Vs[32][128];

    const int tid = threadIdx.x;
    const int b   = blockIdx.z;
    const int q0  = blockIdx.y * QT;
    const int dv0 = blockIdx.x * 128;
    const int kstart = q0 - L0;

    const float* __restrict__ gv = g_qkv + 2ull * BB * SS * UU + (size_t)b * SS * UU;
    const float* __restrict__ gp = g_p + ((size_t)b * SS + q0) * WIN;

    const int tg  = tid >> 5;   // 0..7 -> queries tg*4 .. tg*4+3
    const int col = tid & 31;   // dv cols col + 32j

    float acc[4][4];
#pragma unroll
    for (int a = 0; a < 4; a++)
#pragma unroll
        for (int j = 0; j < 4; j++) acc[a][j] = 0.f;

    for (int kc = 0; kc < WIN / 32; kc++) {
        // Load P tile 32x32
        for (int f = tid; f < 32 * 32; f += 256) {
            const int row = f >> 5, c = f & 31;
            Ps[row][c] = gp[(size_t)row * WIN + kc * 32 + c];
        }
        // Load V tile 32x128 (zero-fill OOB rows)
        for (int f = tid; f < 32 * 32; f += 256) {    // float4 units
            const int row = f >> 5, c4 = f & 31;
            const int j = kstart + kc * 32 + row;
            float4 v = make_float4(0.f, 0.f, 0.f, 0.f);
            if (j >= 0 && j < SS)
                v = *(const float4*)&gv[(size_t)j * UU + dv0 + c4 * 4];
            *(float4*)&Vs[row][c4 * 4] = v;
        }
        __syncthreads();

#pragma unroll 8
        for (int kk = 0; kk < 32; kk++) {
            float p[4], v[4];
#pragma unroll
            for (int a = 0; a < 4; a++) p[a] = Ps[tg * 4 + a][kk];
#pragma unroll
            for (int j = 0; j < 4; j++) v[j] = Vs[kk][col + 32 * j];
#pragma unroll
            for (int a = 0; a < 4; a++)
#pragma unroll
                for (int j = 0; j < 4; j++) acc[a][j] += p[a] * v[j];
        }
        __syncthreads();
    }

#pragma unroll
    for (int a = 0; a < 4; a++) {
        const size_t row = ((size_t)b * SS + q0 + tg * 4 + a) * UU + dv0;
#pragma unroll
        for (int j = 0; j < 4; j++)
            out[row + col + 32 * j] = acc[a][j];
    }
}

// ---------------------------------------------------------------------------
extern "C" void kernel_launch(void* const* d_in, const int* in_sizes, int n_in,
                              void* d_out, int out_size)
{
    const float* x  = (const float*)d_in[0];
    const float* Wq = (const float*)d_in[1];
    const float* Wk = (const float*)d_in[2];
    const float* Wv = (const float*)d_in[3];
    const float* bq = (const float*)d_in[4];
    const float* bk = (const float*)d_in[5];
    const float* bv = (const float*)d_in[6];
    float* out = (float*)d_out;

    cudaFuncSetAttribute(scores_kernel,
                         cudaFuncAttributeMaxDynamicSharedMemorySize, SMEM_SC);

    // 1) QKV projections
    qkv_gemm<<<dim3(UU / 128, BB * SS / 128, 3), 256>>>(x, Wq, Wk, Wv, bq, bk, bv);
    // 2) windowed scores + softmax
    scores_kernel<<<dim3(NT, BB), 256, SMEM_SC>>>();
    // 3) P @ V
    av_kernel<<<dim3(UU / 128, NT, BB), 256>>>(out);
}

// round 3
// speedup vs baseline: 1.6741x; 1.6741x over previous
#include <cuda_runtime.h>
#include <cuda_bf16.h>
#include <cstdint>

#define BB 8
#define SS 2048
#define DD 512
#define UU 512
#define L0 128
#define L1 128
#define QT 32
#define NTIL (SS/QT)
#define WIN 288
#define SCALE 0.044194173824159216f

// ---------------------------------------------------------------------------
// Scratch
// ---------------------------------------------------------------------------
__device__ float g_qkv[3ull * BB * SS * UU];
__device__ float g_p[(size_t)BB * SS * WIN];
__device__ __nv_bfloat16 g_xhi[(size_t)BB * SS * DD];
__device__ __nv_bfloat16 g_xlo[(size_t)BB * SS * DD];
__device__ __nv_bfloat16 g_wthi[3ull * UU * DD];   // transposed: [w][n][k]
__device__ __nv_bfloat16 g_wtlo[3ull * UU * DD];

// ---------------------------------------------------------------------------
// Helpers (all baseline PTX, valid on compute_103)
// ---------------------------------------------------------------------------
__device__ __forceinline__ uint32_t smem_u32(const void* p) {
    uint32_t a;
    asm("{ .reg .u64 t; cvta.to.shared.u64 t, %1; cvt.u32.u64 %0, t; }"
        : "=r"(a) : "l"(p));
    return a;
}
#define SWZ(o) ((o) ^ (((o) >> 3) & 0x70))

__device__ __forceinline__ void cp16(uint32_t s, const void* g) {
    asm volatile("cp.async.cg.shared.global [%0], [%1], 16;" :: "r"(s), "l"(g));
}
#define CP_COMMIT() asm volatile("cp.async.commit_group;" ::: "memory")
#define CP_WAIT(n)  asm volatile("cp.async.wait_group %0;" :: "n"(n) : "memory")

__device__ __forceinline__ void ldm_x4(uint32_t* r, uint32_t a) {
    asm volatile("ldmatrix.sync.aligned.m8n8.x4.shared.b16 {%0,%1,%2,%3}, [%4];"
        : "=r"(r[0]), "=r"(r[1]), "=r"(r[2]), "=r"(r[3]) : "r"(a));
}
__device__ __forceinline__ void ldm_x2(uint32_t* r, uint32_t a) {
    asm volatile("ldmatrix.sync.aligned.m8n8.x2.shared.b16 {%0,%1}, [%2];"
        : "=r"(r[0]), "=r"(r[1]) : "r"(a));
}
__device__ __forceinline__ void mma_bf16(float* d, const uint32_t* a, const uint32_t* b) {
    asm volatile("mma.sync.aligned.m16n8k16.row.col.f32.bf16.bf16.f32 "
        "{%0,%1,%2,%3}, {%4,%5,%6,%7}, {%8,%9}, {%0,%1,%2,%3};"
        : "+f"(d[0]), "+f"(d[1]), "+f"(d[2]), "+f"(d[3])
        : "r"(a[0]), "r"(a[1]), "r"(a[2]), "r"(a[3]), "r"(b[0]), "r"(b[1]));
}

// ---------------------------------------------------------------------------
// Prep: fp32 -> bf16 hi/lo split of X
// ---------------------------------------------------------------------------
__global__ __launch_bounds__(256) void prep_x(const float* __restrict__ x)
{
    const size_t i4 = (size_t)blockIdx.x * 256 + threadIdx.x;
    float4 v = ((const float4*)x)[i4];
    __nv_bfloat16 h0 = __float2bfloat16(v.x), h1 = __float2bfloat16(v.y);
    __nv_bfloat16 h2 = __float2bfloat16(v.z), h3 = __float2bfloat16(v.w);
    __nv_bfloat16 l0 = __float2bfloat16(v.x - __bfloat162float(h0));
    __nv_bfloat16 l1 = __float2bfloat16(v.y - __bfloat162float(h1));
    __nv_bfloat16 l2 = __float2bfloat16(v.z - __bfloat162float(h2));
    __nv_bfloat16 l3 = __float2bfloat16(v.w - __bfloat162float(h3));
    __nv_bfloat162* oh = (__nv_bfloat162*)g_xhi;
    __nv_bfloat162* ol = (__nv_bfloat162*)g_xlo;
    oh[i4 * 2]     = __nv_bfloat162(h0, h1);
    oh[i4 * 2 + 1] = __nv_bfloat162(h2, h3);
    ol[i4 * 2]     = __nv_bfloat162(l0, l1);
    ol[i4 * 2 + 1] = __nv_bfloat162(l2, l3);
}

// ---------------------------------------------------------------------------
// Prep: transpose W[k][n] -> Wt[n][k], bf16 hi/lo
// ---------------------------------------------------------------------------
__global__ __launch_bounds__(256) void prep_w(
    const float* __restrict__ Wq, const float* __restrict__ Wk, const float* __restrict__ Wv)
{
    __shared__ float t[32][33];
    const int w = blockIdx.z;
    const float* __restrict__ W = (w == 0) ? Wq : (w == 1) ? Wk : Wv;
    const int n0 = blockIdx.x * 32;
    const int k0 = blockIdx.y * 32;
    const int tx = threadIdx.x & 31;
    const int ty = threadIdx.x >> 5;
#pragma unroll
    for (int i = 0; i < 4; i++) {
        const int r = ty + i * 8;
        t[r][tx] = W[(size_t)(k0 + r) * UU + n0 + tx];
    }
    __syncthreads();
    const size_t base = (size_t)w * UU * DD;
#pragma unroll
    for (int i = 0; i < 4; i++) {
        const int r = ty + i * 8;
        const float v = t[tx][r];
        __nv_bfloat16 h = __float2bfloat16(v);
        __nv_bfloat16 l = __float2bfloat16(v - __bfloat162float(h));
        g_wthi[base + (size_t)(n0 + r) * DD + k0 + tx] = h;
        g_wtlo[base + (size_t)(n0 + r) * DD + k0 + tx] = l;
    }
}

// ---------------------------------------------------------------------------
// QKV GEMM on mma.sync bf16 (hi/lo 3-pass split).
// CTA: 128(M) x 128(N), K=512 in 8 chunks of 64. 8 warps, warp tile 32x64.
// cp.async double-buffered SMEM, SW128 swizzle, ldmatrix fragments.
// grid: (UU/128=4, 16384/128=128, 3), 256 threads.
// ---------------------------------------------------------------------------
#define OFF_AH 0
#define OFF_AL 16384
#define OFF_BH 32768
#define OFF_BL 49152
#define BUFB   65536
#define GEMM_SMEM (2 * BUFB)

__global__ __launch_bounds__(256, 1) void qkv_tc(
    const float* __restrict__ bq, const float* __restrict__ bk, const float* __restrict__ bv)
{
    extern __shared__ char sm[];
    const uint32_t sbase = smem_u32(sm);
    const int tid  = threadIdx.x;
    const int warp = tid >> 5;
    const int lane = tid & 31;
    const int w3 = blockIdx.z;
    const int n0 = blockIdx.x * 128;
    const int m0 = blockIdx.y * 128;

    const int wm = (warp & 3) * 32;   // warp M offset within CTA tile
    const int wn = (warp >> 2) * 64;  // warp N offset

    const __nv_bfloat16* __restrict__ xh = g_xhi + (size_t)m0 * DD;
    const __nv_bfloat16* __restrict__ xl = g_xlo + (size_t)m0 * DD;
    const __nv_bfloat16* __restrict__ wh = g_wthi + (size_t)w3 * UU * DD + (size_t)n0 * DD;
    const __nv_bfloat16* __restrict__ wl = g_wtlo + (size_t)w3 * UU * DD + (size_t)n0 * DD;

    // Per-thread copy slice: 4 x 16B chunks per array per kchunk
    const int crow0 = tid >> 1;            // rows tid/2 and tid/2 + ... pattern below
    // We use f = tid + i*256 over 1024 chunks: row = f>>3, seg = (f&7)*16

    // --- issue cp.async for one k-chunk ---
    auto issue_chunk = [&](int c, int buf) {
        const int kc0 = c * 64;
        const uint32_t bs = sbase + buf * BUFB;
#pragma unroll
        for (int i = 0; i < 4; i++) {
            const int f = tid + i * 256;
            const int row = f >> 3, seg = (f & 7) * 16;
            const uint32_t so = SWZ(row * 128 + seg);
            const char* ah = (const char*)(xh + (size_t)row * DD + kc0) + seg;
            const char* al = (const char*)(xl + (size_t)row * DD + kc0) + seg;
            const char* bh = (const char*)(wh + (size_t)row * DD + kc0) + seg;
            const char* bl = (const char*)(wl + (size_t)row * DD + kc0) + seg;
            cp16(bs + OFF_AH + so, ah);
            cp16(bs + OFF_AL + so, al);
            cp16(bs + OFF_BH + so, bh);
            cp16(bs + OFF_BL + so, bl);
        }
        CP_COMMIT();
    };

    float acc[2][8][4];
#pragma unroll
    for (int mt = 0; mt < 2; mt++)
#pragma unroll
        for (int nt = 0; nt < 8; nt++)
#pragma unroll
            for (int i = 0; i < 4; i++) acc[mt][nt][i] = 0.f;

    issue_chunk(0, 0);

    // ldmatrix lane addressing
    const int lsub = lane >> 3;        // 0..3
    const int lrow = lane & 7;
    const int a_row_off = (lsub & 1) * 8;     // +8 rows for sub 1,3
    const int a_k_off   = (lsub >> 1) * 16;   // +16B for sub 2,3
    const int b_k_off   = (lsub & 1) * 16;    // x2: sub parity picks k half

    for (int c = 0; c < 8; c++) {
        if (c < 7) issue_chunk(c + 1, (c + 1) & 1);
        if (c < 7) { CP_WAIT(1); } else { CP_WAIT(0); }
        __syncthreads();

        const uint32_t bs = sbase + (c & 1) * BUFB;
        const uint32_t Ah = bs + OFF_AH, Al = bs + OFF_AL;
        const uint32_t Bh = bs + OFF_BH, Bl = bs + OFF_BL;

#pragma unroll
        for (int ks = 0; ks < 4; ks++) {
            const int kb = ks * 32;   // byte offset of this k16 step
            uint32_t ah[2][4], al[2][4];
#pragma unroll
            for (int mt = 0; mt < 2; mt++) {
                const int row = wm + mt * 16 + lrow + a_row_off;
                const uint32_t off = SWZ(row * 128 + kb + a_k_off);
                ldm_x4(ah[mt], Ah + off);
                ldm_x4(al[mt], Al + off);
            }
#pragma unroll
            for (int nt = 0; nt < 8; nt++) {
                const int nrow = wn + nt * 8 + lrow;
                const uint32_t off = SWZ(nrow * 128 + kb + b_k_off);
                uint32_t bh[2], bl[2];
                ldm_x2(bh, Bh + off);
                ldm_x2(bl, Bl + off);
#pragma unroll
                for (int mt = 0; mt < 2; mt++) {
                    mma_bf16(acc[mt][nt], ah[mt], bh);
                    mma_bf16(acc[mt][nt], ah[mt], bl);
                    mma_bf16(acc[mt][nt], al[mt], bh);
                }
            }
        }
        __syncthreads();
    }

    // Epilogue: registers -> GMEM with bias
    const float* __restrict__ bias = (w3 == 0) ? bq : (w3 == 1) ? bk : bv;
    float* __restrict__ out = g_qkv + (size_t)w3 * BB * SS * UU;
    const int grp = lane >> 2;
    const int qd  = lane & 3;
#pragma unroll
    for (int nt = 0; nt < 8; nt++) {
        const int col = n0 + wn + nt * 8 + qd * 2;
        const float b0 = bias[col], b1 = bias[col + 1];
#pragma unroll
        for (int mt = 0; mt < 2; mt++) {
            const int r0 = m0 + wm + mt * 16 + grp;
            float2 v0 = make_float2(acc[mt][nt][0] + b0, acc[mt][nt][1] + b1);
            float2 v1 = make_float2(acc[mt][nt][2] + b0, acc[mt][nt][3] + b1);
            *(float2*)&out[(size_t)r0 * UU + col]       = v0;
            *(float2*)&out[(size_t)(r0 + 8) * UU + col] = v1;
        }
    }
}

// ---------------------------------------------------------------------------
// Kernel 2: windowed scores + masked softmax (unchanged from passing R1)
// ---------------------------------------------------------------------------
#define QSTR 516
#define KSTR 65
#define SMEM_SC ((32*QSTR + 32*KSTR + 32*WIN) * 4)

__global__ __launch_bounds__(256) void scores_kernel()
{
    extern __shared__ float smf[];
    float* Qs = smf;
    float* Ks = Qs + 32 * QSTR;
    float* Sx = Ks + 32 * KSTR;

    const int tid = threadIdx.x;
    const int b   = blockIdx.y;
    const int q0  = blockIdx.x * QT;
    const int kstart = q0 - L0;

    const float* __restrict__ gq = g_qkv + (size_t)(b * SS + q0) * UU;
    const float* __restrict__ gk = g_qkv + (size_t)BB * SS * UU + (size_t)b * SS * UU;

    for (int f = tid; f < 32 * 128; f += 256) {
        const int row = f >> 7, c4 = f & 127;
        float4 v = *(const float4*)&gq[(size_t)row * UU + c4 * 4];
        *(float4*)&Qs[row * QSTR + c4 * 4] = v;
    }
    __syncthreads();

    const int ty = tid >> 4;
    const int tx = tid & 15;

    for (int kc = 0; kc < WIN / 32; kc++) {
        float a00 = 0.f, a01 = 0.f, a10 = 0.f, a11 = 0.f;
        const int kbase = kstart + kc * 32;

        for (int dc = 0; dc < DD; dc += 64) {
            for (int f = tid; f < 32 * 16; f += 256) {
                const int row = f >> 4, c4 = f & 15;
                const int j = kbase + row;
                float4 v = make_float4(0.f, 0.f, 0.f, 0.f);
                if (j >= 0 && j < SS)
                    v = *(const float4*)&gk[(size_t)j * UU + dc + c4 * 4];
                float* p = &Ks[row * KSTR + c4 * 4];
                p[0] = v.x; p[1] = v.y; p[2] = v.z; p[3] = v.w;
            }
            __syncthreads();

            const float* q0p = &Qs[(2 * ty) * QSTR + dc];
            const float* q1p = &Qs[(2 * ty + 1) * QSTR + dc];
            const float* k0p = &Ks[(2 * tx) * KSTR];
            const float* k1p = &Ks[(2 * tx + 1) * KSTR];
#pragma unroll 16
            for (int d = 0; d < 64; d++) {
                const float qa = q0p[d], qb = q1p[d];
                const float ka = k0p[d], kb = k1p[d];
                a00 += qa * ka; a01 += qa * kb;
                a10 += qb * ka; a11 += qb * kb;
            }
            __syncthreads();
        }
        Sx[(2 * ty)     * WIN + kc * 32 + 2 * tx]     = a00 * SCALE;
        Sx[(2 * ty)     * WIN + kc * 32 + 2 * tx + 1] = a01 * SCALE;
        Sx[(2 * ty + 1) * WIN + kc * 32 + 2 * tx]     = a10 * SCALE;
        Sx[(2 * ty + 1) * WIN + kc * 32 + 2 * tx + 1] = a11 * SCALE;
    }
    __syncthreads();

    const int lane = tid & 31;
    for (int rr = tid >> 5; rr < QT; rr += 8) {
        const int i = q0 + rr;
        int cmin = rr;
        if (-kstart > cmin) cmin = -kstart;
        int cmax = rr + L0 + L1;
        const int chi = SS - 1 - kstart;
        if (chi < cmax) cmax = chi;

        float mx = -1e30f;
        for (int c = lane; c < WIN; c += 32)
            if (c >= cmin && c <= cmax) mx = fmaxf(mx, Sx[rr * WIN + c]);
#pragma unroll
        for (int off = 16; off > 0; off >>= 1)
            mx = fmaxf(mx, __shfl_xor_sync(0xFFFFFFFFu, mx, off));

        float sum = 0.f;
        for (int c = lane; c < WIN; c += 32) {
            float e = 0.f;
            if (c >= cmin && c <= cmax) e = __expf(Sx[rr * WIN + c] - mx);
            Sx[rr * WIN + c] = e;
            sum += e;
        }
#pragma unroll
        for (int off = 16; off > 0; off >>= 1)
            sum += __shfl_xor_sync(0xFFFFFFFFu, sum, off);

        const float inv = 1.0f / sum;
        float* __restrict__ prow = &g_p[((size_t)b * SS + i) * WIN];
        for (int c = lane; c < WIN; c += 32)
            prow[c] = Sx[rr * WIN + c] * inv;
    }
}

// ---------------------------------------------------------------------------
// Kernel 3: out = P @ V (unchanged)
// ---------------------------------------------------------------------------
__global__ __launch_bounds__(256) void av_kernel(float* __restrict__ out)
{
    __shared__ float Ps[32][32];
    __shared__ float Vs[32][128];

    const int tid = threadIdx.x;
    const int b   = blockIdx.z;
    const int q0  = blockIdx.y * QT;
    const int dv0 = blockIdx.x * 128;
    const int kstart = q0 - L0;

    const float* __restrict__ gv = g_qkv + 2ull * BB * SS * UU + (size_t)b * SS * UU;
    const float* __restrict__ gp = g_p + ((size_t)b * SS + q0) * WIN;

    const int tg  = tid >> 5;
    const int col = tid & 31;

    float acc[4][4];
#pragma unroll
    for (int a = 0; a < 4; a++)
#pragma unroll
        for (int j = 0; j < 4; j++) acc[a][j] = 0.f;

    for (int kc = 0; kc < WIN / 32; kc++) {
        for (int f = tid; f < 32 * 32; f += 256) {
            const int row = f >> 5, c = f & 31;
            Ps[row][c] = gp[(size_t)row * WIN + kc * 32 + c];
        }
        for (int f = tid; f < 32 * 32; f += 256) {
            const int row = f >> 5, c4 = f & 31;
            const int j = kstart + kc * 32 + row;
            float4 v = make_float4(0.f, 0.f, 0.f, 0.f);
            if (j >= 0 && j < SS)
                v = *(const float4*)&gv[(size_t)j * UU + dv0 + c4 * 4];
            *(float4*)&Vs[row][c4 * 4] = v;
        }
        __syncthreads();

#pragma unroll 8
        for (int kk = 0; kk < 32; kk++) {
            float p[4], v[4];
#pragma unroll
            for (int a = 0; a < 4; a++) p[a] = Ps[tg * 4 + a][kk];
#pragma unroll
            for (int j = 0; j < 4; j++) v[j] = Vs[kk][col + 32 * j];
#pragma unroll
            for (int a = 0; a < 4; a++)
#pragma unroll
                for (int j = 0; j < 4; j++) acc[a][j] += p[a] * v[j];
        }
        __syncthreads();
    }

#pragma unroll
    for (int a = 0; a < 4; a++) {
        const size_t row = ((size_t)b * SS + q0 + tg * 4 + a) * UU + dv0;
#pragma unroll
        for (int j = 0; j < 4; j++)
            out[row + col + 32 * j] = acc[a][j];
    }
}

// ---------------------------------------------------------------------------
extern "C" void kernel_launch(void* const* d_in, const int* in_sizes, int n_in,
                              void* d_out, int out_size)
{
    const float* x  = (const float*)d_in[0];
    const float* Wq = (const float*)d_in[1];
    const float* Wk = (const float*)d_in[2];
    const float* Wv = (const float*)d_in[3];
    const float* bq = (const float*)d_in[4];
    const float* bk = (const float*)d_in[5];
    const float* bv = (const float*)d_in[6];
    float* out = (float*)d_out;

    cudaFuncSetAttribute(scores_kernel,
                         cudaFuncAttributeMaxDynamicSharedMemorySize, SMEM_SC);
    cudaFuncSetAttribute(qkv_tc,
                         cudaFuncAttributeMaxDynamicSharedMemorySize, GEMM_SMEM);

    prep_x<<<(BB * SS * DD / 4) / 256, 256>>>(x);
    prep_w<<<dim3(UU / 32, DD / 32, 3), 256>>>(Wq, Wk, Wv);
    qkv_tc<<<dim3(UU / 128, BB * SS / 128, 3), 256, GEMM_SMEM>>>(bq, bk, bv);
    scores_kernel<<<dim3(NTIL, BB), 256, SMEM_SC>>>();
    av_kernel<<<dim3(UU / 128, NTIL, BB), 256>>>(out);
}

// round 4
// speedup vs baseline: 3.3935x; 2.0270x over previous
#include <cuda_runtime.h>
#include <cuda_bf16.h>
#include <cstdint>

#define BB 8
#define SS 2048
#define DD 512
#define UU 512
#define QT2 64                 // queries per scores/av tile
#define NT2 (SS/QT2)           // 32
#define WIN2 320               // 64 + 256 window span
#define SCALE 0.044194173824159216f

// ---------------------------------------------------------------------------
// Scratch (bf16 hi/lo everywhere)
// ---------------------------------------------------------------------------
__device__ __nv_bfloat16 g_xhi[(size_t)BB * SS * DD];
__device__ __nv_bfloat16 g_xlo[(size_t)BB * SS * DD];
__device__ __nv_bfloat16 g_wthi[3ull * UU * DD];
__device__ __nv_bfloat16 g_wtlo[3ull * UU * DD];
__device__ __nv_bfloat16 g_qh[(size_t)BB * SS * UU];
__device__ __nv_bfloat16 g_ql[(size_t)BB * SS * UU];
__device__ __nv_bfloat16 g_kh[(size_t)BB * SS * UU];
__device__ __nv_bfloat16 g_kl[(size_t)BB * SS * UU];
__device__ __nv_bfloat16 g_vh[(size_t)BB * SS * UU];
__device__ __nv_bfloat16 g_vl[(size_t)BB * SS * UU];
__device__ __nv_bfloat16 g_ph[(size_t)BB * SS * WIN2];
__device__ __nv_bfloat16 g_pl[(size_t)BB * SS * WIN2];

// ---------------------------------------------------------------------------
// Helpers (baseline PTX only — valid under compute_103)
// ---------------------------------------------------------------------------
__device__ __forceinline__ uint32_t smem_u32(const void* p) {
    uint32_t a;
    asm("{ .reg .u64 t; cvta.to.shared.u64 t, %1; cvt.u32.u64 %0, t; }"
        : "=r"(a) : "l"(p));
    return a;
}
#define SWZ(o) ((o) ^ (((o) >> 3) & 0x70))

__device__ __forceinline__ void cp16(uint32_t s, const void* g) {
    asm volatile("cp.async.cg.shared.global [%0], [%1], 16;" :: "r"(s), "l"(g));
}
#define CP_COMMIT() asm volatile("cp.async.commit_group;" ::: "memory")
#define CP_WAIT(n)  asm volatile("cp.async.wait_group %0;" :: "n"(n) : "memory")

__device__ __forceinline__ void ldm_x4(uint32_t* r, uint32_t a) {
    asm volatile("ldmatrix.sync.aligned.m8n8.x4.shared.b16 {%0,%1,%2,%3}, [%4];"
        : "=r"(r[0]), "=r"(r[1]), "=r"(r[2]), "=r"(r[3]) : "r"(a));
}
__device__ __forceinline__ void ldm_x4t(uint32_t* r, uint32_t a) {
    asm volatile("ldmatrix.sync.aligned.m8n8.x4.trans.shared.b16 {%0,%1,%2,%3}, [%4];"
        : "=r"(r[0]), "=r"(r[1]), "=r"(r[2]), "=r"(r[3]) : "r"(a));
}
__device__ __forceinline__ void ldm_x2(uint32_t* r, uint32_t a) {
    asm volatile("ldmatrix.sync.aligned.m8n8.x2.shared.b16 {%0,%1}, [%2];"
        : "=r"(r[0]), "=r"(r[1]) : "r"(a));
}
__device__ __forceinline__ void mma_bf16(float* d, const uint32_t* a, const uint32_t* b) {
    asm volatile("mma.sync.aligned.m16n8k16.row.col.f32.bf16.bf16.f32 "
        "{%0,%1,%2,%3}, {%4,%5,%6,%7}, {%8,%9}, {%0,%1,%2,%3};"
        : "+f"(d[0]), "+f"(d[1]), "+f"(d[2]), "+f"(d[3])
        : "r"(a[0]), "r"(a[1]), "r"(a[2]), "r"(a[3]), "r"(b[0]), "r"(b[1]));
}
__device__ __forceinline__ int iclamp(int v, int lo, int hi) {
    return v < lo ? lo : (v > hi ? hi : v);
}

// ---------------------------------------------------------------------------
// Prep: fp32 -> bf16 hi/lo split of X
// ---------------------------------------------------------------------------
__global__ __launch_bounds__(256) void prep_x(const float* __restrict__ x)
{
    const size_t i4 = (size_t)blockIdx.x * 256 + threadIdx.x;
    float4 v = ((const float4*)x)[i4];
    __nv_bfloat16 h0 = __float2bfloat16(v.x), h1 = __float2bfloat16(v.y);
    __nv_bfloat16 h2 = __float2bfloat16(v.z), h3 = __float2bfloat16(v.w);
    __nv_bfloat16 l0 = __float2bfloat16(v.x - __bfloat162float(h0));
    __nv_bfloat16 l1 = __float2bfloat16(v.y - __bfloat162float(h1));
    __nv_bfloat16 l2 = __float2bfloat16(v.z - __bfloat162float(h2));
    __nv_bfloat16 l3 = __float2bfloat16(v.w - __bfloat162float(h3));
    __nv_bfloat162* oh = (__nv_bfloat162*)g_xhi;
    __nv_bfloat162* ol = (__nv_bfloat162*)g_xlo;
    oh[i4 * 2]     = __nv_bfloat162(h0, h1);
    oh[i4 * 2 + 1] = __nv_bfloat162(h2, h3);
    ol[i4 * 2]     = __nv_bfloat162(l0, l1);
    ol[i4 * 2 + 1] = __nv_bfloat162(l2, l3);
}

// ---------------------------------------------------------------------------
// Prep: transpose W[k][n] -> Wt[n][k], bf16 hi/lo
// ---------------------------------------------------------------------------
__global__ __launch_bounds__(256) void prep_w(
    const float* __restrict__ Wq, const float* __restrict__ Wk, const float* __restrict__ Wv)
{
    __shared__ float t[32][33];
    const int w = blockIdx.z;
    const float* __restrict__ W = (w == 0) ? Wq : (w == 1) ? Wk : Wv;
    const int n0 = blockIdx.x * 32;
    const int k0 = blockIdx.y * 32;
    const int tx = threadIdx.x & 31;
    const int ty = threadIdx.x >> 5;
#pragma unroll
    for (int i = 0; i < 4; i++) {
        const int r = ty + i * 8;
        t[r][tx] = W[(size_t)(k0 + r) * UU + n0 + tx];
    }
    __syncthreads();
    const size_t base = (size_t)w * UU * DD;
#pragma unroll
    for (int i = 0; i < 4; i++) {
        const int r = ty + i * 8;
        const float v = t[tx][r];
        __nv_bfloat16 h = __float2bfloat16(v);
        __nv_bfloat16 l = __float2bfloat16(v - __bfloat162float(h));
        g_wthi[base + (size_t)(n0 + r) * DD + k0 + tx] = h;
        g_wtlo[base + (size_t)(n0 + r) * DD + k0 + tx] = l;
    }
}

// ---------------------------------------------------------------------------
// QKV GEMM (mma.sync bf16, hi/lo 3-pass). Epilogue now writes bf16 hi/lo
// q/k/v directly. grid: (4, 128, 3), 256 threads.
// ---------------------------------------------------------------------------
#define OFF_AH 0
#define OFF_AL 16384
#define OFF_BH 32768
#define OFF_BL 49152
#define BUFB   65536
#define GEMM_SMEM (2 * BUFB)

__global__ __launch_bounds__(256, 1) void qkv_tc(
    const float* __restrict__ bq, const float* __restrict__ bk, const float* __restrict__ bv)
{
    extern __shared__ char sm[];
    const uint32_t sbase = smem_u32(sm);
    const int tid  = threadIdx.x;
    const int warp = tid >> 5;
    const int lane = tid & 31;
    const int w3 = blockIdx.z;
    const int n0 = blockIdx.x * 128;
    const int m0 = blockIdx.y * 128;

    const int wm = (warp & 3) * 32;
    const int wn = (warp >> 2) * 64;

    const __nv_bfloat16* __restrict__ xh = g_xhi + (size_t)m0 * DD;
    const __nv_bfloat16* __restrict__ xl = g_xlo + (size_t)m0 * DD;
    const __nv_bfloat16* __restrict__ wh = g_wthi + (size_t)w3 * UU * DD + (size_t)n0 * DD;
    const __nv_bfloat16* __restrict__ wl = g_wtlo + (size_t)w3 * UU * DD + (size_t)n0 * DD;

    auto issue_chunk = [&](int c, int buf) {
        const int kc0 = c * 64;
        const uint32_t bs = sbase + buf * BUFB;
#pragma unroll
        for (int i = 0; i < 4; i++) {
            const int f = tid + i * 256;
            const int row = f >> 3, seg = (f & 7) * 16;
            const uint32_t so = SWZ(row * 128 + seg);
            cp16(bs + OFF_AH + so, (const char*)(xh + (size_t)row * DD + kc0) + seg);
            cp16(bs + OFF_AL + so, (const char*)(xl + (size_t)row * DD + kc0) + seg);
            cp16(bs + OFF_BH + so, (const char*)(wh + (size_t)row * DD + kc0) + seg);
            cp16(bs + OFF_BL + so, (const char*)(wl + (size_t)row * DD + kc0) + seg);
        }
        CP_COMMIT();
    };

    float acc[2][8][4];
#pragma unroll
    for (int mt = 0; mt < 2; mt++)
#pragma unroll
        for (int nt = 0; nt < 8; nt++)
#pragma unroll
            for (int i = 0; i < 4; i++) acc[mt][nt][i] = 0.f;

    issue_chunk(0, 0);

    const int lsub = lane >> 3;
    const int lrow = lane & 7;
    const int a_row_off = (lsub & 1) * 8;
    const int a_k_off   = (lsub >> 1) * 16;
    const int b_k_off   = (lsub & 1) * 16;

    for (int c = 0; c < 8; c++) {
        if (c < 7) { issue_chunk(c + 1, (c + 1) & 1); CP_WAIT(1); }
        else       { CP_WAIT(0); }
        __syncthreads();

        const uint32_t bs = sbase + (c & 1) * BUFB;
        const uint32_t Ah = bs + OFF_AH, Al = bs + OFF_AL;
        const uint32_t Bh = bs + OFF_BH, Bl = bs + OFF_BL;

#pragma unroll
        for (int ks = 0; ks < 4; ks++) {
            const int kb = ks * 32;
            uint32_t ah[2][4], al[2][4];
#pragma unroll
            for (int mt = 0; mt < 2; mt++) {
                const int row = wm + mt * 16 + lrow + a_row_off;
                const uint32_t off = SWZ(row * 128 + kb + a_k_off);
                ldm_x4(ah[mt], Ah + off);
                ldm_x4(al[mt], Al + off);
            }
#pragma unroll
            for (int nt = 0; nt < 8; nt++) {
                const int nrow = wn + nt * 8 + lrow;
                const uint32_t off = SWZ(nrow * 128 + kb + b_k_off);
                uint32_t bh[2], bl[2];
                ldm_x2(bh, Bh + off);
                ldm_x2(bl, Bl + off);
#pragma unroll
                for (int mt = 0; mt < 2; mt++) {
                    mma_bf16(acc[mt][nt], ah[mt], bh);
                    mma_bf16(acc[mt][nt], ah[mt], bl);
                    mma_bf16(acc[mt][nt], al[mt], bh);
                }
            }
        }
        __syncthreads();
    }

    // Epilogue: +bias, split hi/lo, store bf16
    const float* __restrict__ bias = (w3 == 0) ? bq : (w3 == 1) ? bk : bv;
    __nv_bfloat16* __restrict__ oh = (w3 == 0) ? g_qh : (w3 == 1) ? g_kh : g_vh;
    __nv_bfloat16* __restrict__ ol = (w3 == 0) ? g_ql : (w3 == 1) ? g_kl : g_vl;
    const int grp = lane >> 2;
    const int qd  = lane & 3;
#pragma unroll
    for (int nt = 0; nt < 8; nt++) {
        const int col = n0 + wn + nt * 8 + qd * 2;
        const float b0 = bias[col], b1 = bias[col + 1];
#pragma unroll
        for (int mt = 0; mt < 2; mt++) {
            const int r0 = m0 + wm + mt * 16 + grp;
            const float f0 = acc[mt][nt][0] + b0, f1 = acc[mt][nt][1] + b1;
            const float f2 = acc[mt][nt][2] + b0, f3 = acc[mt][nt][3] + b1;
            __nv_bfloat16 h0 = __float2bfloat16(f0), h1 = __float2bfloat16(f1);
            __nv_bfloat16 h2 = __float2bfloat16(f2), h3 = __float2bfloat16(f3);
            *(__nv_bfloat162*)&oh[(size_t)r0 * UU + col] = __nv_bfloat162(h0, h1);
            *(__nv_bfloat162*)&ol[(size_t)r0 * UU + col] = __nv_bfloat162(
                __float2bfloat16(f0 - __bfloat162float(h0)),
                __float2bfloat16(f1 - __bfloat162float(h1)));
            *(__nv_bfloat162*)&oh[(size_t)(r0 + 8) * UU + col] = __nv_bfloat162(h2, h3);
            *(__nv_bfloat162*)&ol[(size_t)(r0 + 8) * UU + col] = __nv_bfloat162(
                __float2bfloat16(f2 - __bfloat162float(h2)),
                __float2bfloat16(f3 - __bfloat162float(h3)));
        }
    }
}

// ---------------------------------------------------------------------------
// scores_mma: S[64 x 320] = Q K^T (3-pass hi/lo mma) + masked softmax,
// P written bf16 hi/lo. grid (32, 8), 256 threads, 192 KB smem.
// ---------------------------------------------------------------------------
#define SC_AH 0
#define SC_AL 8192
#define SC_BH 16384
#define SC_BL 57344
#define SC_BUF 98304
#define SC_SMEM (2 * SC_BUF)
#define SSTR 321

__global__ __launch_bounds__(256, 1) void scores_mma()
{
    extern __shared__ char sm[];
    const uint32_t sbase = smem_u32(sm);
    const int tid  = threadIdx.x;
    const int warp = tid >> 5;
    const int lane = tid & 31;
    const int b  = blockIdx.y;
    const int q0 = blockIdx.x * QT2;
    const int kstart = q0 - 128;

    const __nv_bfloat16* __restrict__ qh = g_qh + (size_t)(b * SS + q0) * UU;
    const __nv_bfloat16* __restrict__ ql = g_ql + (size_t)(b * SS + q0) * UU;
    const __nv_bfloat16* __restrict__ kh = g_kh + (size_t)b * SS * UU;
    const __nv_bfloat16* __restrict__ kl = g_kl + (size_t)b * SS * UU;

    auto issue = [&](int c, int buf) {
        const int kc0 = c * 64;
        const uint32_t bs = sbase + buf * SC_BUF;
#pragma unroll
        for (int i = 0; i < 2; i++) {
            const int f = tid + i * 256;
            const int row = f >> 3, seg = (f & 7) * 16;
            const uint32_t so = SWZ(row * 128 + seg);
            cp16(bs + SC_AH + so, (const char*)(qh + (size_t)row * UU + kc0) + seg);
            cp16(bs + SC_AL + so, (const char*)(ql + (size_t)row * UU + kc0) + seg);
        }
#pragma unroll
        for (int i = 0; i < 10; i++) {
            const int f = tid + i * 256;
            const int row = f >> 3, seg = (f & 7) * 16;
            const int j = iclamp(kstart + row, 0, SS - 1);
            const uint32_t so = SWZ(row * 128 + seg);
            cp16(bs + SC_BH + so, (const char*)(kh + (size_t)j * UU + kc0) + seg);
            cp16(bs + SC_BL + so, (const char*)(kl + (size_t)j * UU + kc0) + seg);
        }
        CP_COMMIT();
    };

    float acc[2][10][4];
#pragma unroll
    for (int mt = 0; mt < 2; mt++)
#pragma unroll
        for (int nt = 0; nt < 10; nt++)
#pragma unroll
            for (int i = 0; i < 4; i++) acc[mt][nt][i] = 0.f;

    issue(0, 0);

    const int lsub = lane >> 3;
    const int lrow = lane & 7;
    const int a_ro = (lsub & 1) * 8;
    const int a_ko = (lsub >> 1) * 16;
    const int b_ro = (lsub >> 1) * 8;
    const int b_ko = (lsub & 1) * 16;
    const int wm = (warp & 1) * 32;
    const int wn = (warp >> 1) * 80;

    for (int c = 0; c < 8; c++) {
        if (c < 7) { issue(c + 1, (c + 1) & 1); CP_WAIT(1); }
        else       { CP_WAIT(0); }
        __syncthreads();

        const uint32_t bs = sbase + (c & 1) * SC_BUF;
#pragma unroll
        for (int ks = 0; ks < 4; ks++) {
            const int kb = ks * 32;
            uint32_t ah[2][4], al[2][4];
#pragma unroll
            for (int mt = 0; mt < 2; mt++) {
                const uint32_t off = SWZ((wm + mt * 16 + lrow + a_ro) * 128 + kb + a_ko);
                ldm_x4(ah[mt], bs + SC_AH + off);
                ldm_x4(al[mt], bs + SC_AL + off);
            }
#pragma unroll
            for (int ntp = 0; ntp < 5; ntp++) {
                const uint32_t off = SWZ((wn + ntp * 16 + b_ro + lrow) * 128 + kb + b_ko);
                uint32_t bh[4], bl[4];
                ldm_x4(bh, bs + SC_BH + off);
                ldm_x4(bl, bs + SC_BL + off);
#pragma unroll
                for (int t = 0; t < 2; t++) {
#pragma unroll
                    for (int mt = 0; mt < 2; mt++) {
                        mma_bf16(acc[mt][ntp * 2 + t], ah[mt], bh + t * 2);
                        mma_bf16(acc[mt][ntp * 2 + t], ah[mt], bl + t * 2);
                        mma_bf16(acc[mt][ntp * 2 + t], al[mt], bh + t * 2);
                    }
                }
            }
        }
        __syncthreads();
    }

    // S -> smem (scaled)
    float* Ss = (float*)sm;
    const int grp = lane >> 2;
    const int qd  = lane & 3;
#pragma unroll
    for (int mt = 0; mt < 2; mt++) {
        const int r0 = wm + mt * 16 + grp;
#pragma unroll
        for (int nt = 0; nt < 10; nt++) {
            const int col = wn + nt * 8 + qd * 2;
            Ss[r0 * SSTR + col]           = acc[mt][nt][0] * SCALE;
            Ss[r0 * SSTR + col + 1]       = acc[mt][nt][1] * SCALE;
            Ss[(r0 + 8) * SSTR + col]     = acc[mt][nt][2] * SCALE;
            Ss[(r0 + 8) * SSTR + col + 1] = acc[mt][nt][3] * SCALE;
        }
    }
    __syncthreads();

    // Masked softmax, write P bf16 hi/lo (masked -> 0)
    __nv_bfloat16* __restrict__ oph = g_ph + (size_t)(b * SS + q0) * WIN2;
    __nv_bfloat16* __restrict__ opl = g_pl + (size_t)(b * SS + q0) * WIN2;
#pragma unroll
    for (int r8 = 0; r8 < 8; r8++) {
        const int rr = warp * 8 + r8;
        const int cmin = (rr > -kstart) ? rr : -kstart;
        int cmax = rr + 256;
        const int chi = SS - 1 - kstart;
        if (chi < cmax) cmax = chi;

        float mx = -1e30f;
        for (int c = lane; c < WIN2; c += 32)
            if (c >= cmin && c <= cmax) mx = fmaxf(mx, Ss[rr * SSTR + c]);
#pragma unroll
        for (int off = 16; off > 0; off >>= 1)
            mx = fmaxf(mx, __shfl_xor_sync(0xFFFFFFFFu, mx, off));

        float sum = 0.f;
        for (int c = lane; c < WIN2; c += 32) {
            float e = 0.f;
            if (c >= cmin && c <= cmax) e = __expf(Ss[rr * SSTR + c] - mx);
            Ss[rr * SSTR + c] = e;
            sum += e;
        }
#pragma unroll
        for (int off = 16; off > 0; off >>= 1)
            sum += __shfl_xor_sync(0xFFFFFFFFu, sum, off);

        const float inv = 1.0f / sum;
        for (int c = lane; c < WIN2; c += 32) {
            const float p = Ss[rr * SSTR + c] * inv;
            const __nv_bfloat16 h = __float2bfloat16(p);
            oph[(size_t)rr * WIN2 + c] = h;
            opl[(size_t)rr * WIN2 + c] = __float2bfloat16(p - __bfloat162float(h));
        }
    }
}

// ---------------------------------------------------------------------------
// av_mma: out[64 x 512] = P V (3-pass hi/lo mma, V via ldmatrix.trans).
// grid (32, 8), 256 threads, 96 KB smem.
// ---------------------------------------------------------------------------
#define AV_PH  0
#define AV_PL  8192
#define AV_V0H 16384
#define AV_V0L 24576
#define AV_V1H 32768
#define AV_V1L 40960
#define AV_BUF 49152
#define AV_SMEM (2 * AV_BUF)

__global__ __launch_bounds__(256, 1) void av_mma(float* __restrict__ out)
{
    extern __shared__ char sm[];
    const uint32_t sbase = smem_u32(sm);
    const int tid  = threadIdx.x;
    const int warp = tid >> 5;
    const int lane = tid & 31;
    const int b  = blockIdx.y;
    const int q0 = blockIdx.x * QT2;
    const int kstart = q0 - 128;

    const __nv_bfloat16* __restrict__ gph = g_ph + (size_t)(b * SS + q0) * WIN2;
    const __nv_bfloat16* __restrict__ gpl = g_pl + (size_t)(b * SS + q0) * WIN2;
    const __nv_bfloat16* __restrict__ vh = g_vh + (size_t)b * SS * UU;
    const __nv_bfloat16* __restrict__ vl = g_vl + (size_t)b * SS * UU;

    auto issue = [&](int dc, int kc, int buf) {
        const uint32_t bs = sbase + buf * AV_BUF;
#pragma unroll
        for (int i = 0; i < 2; i++) {
            const int f = tid + i * 256;
            const int row = f >> 3, seg = (f & 7) * 16;
            const uint32_t so = SWZ(row * 128 + seg);
            cp16(bs + AV_PH + so, (const char*)(gph + (size_t)row * WIN2 + kc * 64) + seg);
            cp16(bs + AV_PL + so, (const char*)(gpl + (size_t)row * WIN2 + kc * 64) + seg);
        }
#pragma unroll
        for (int i = 0; i < 2; i++) {
            const int f = tid + i * 256;
            const int row = f >> 3, seg = (f & 7) * 16;
            const int j = iclamp(kstart + kc * 64 + row, 0, SS - 1);
            const uint32_t so = SWZ(row * 128 + seg);
            const int d0 = dc * 128;
            cp16(bs + AV_V0H + so, (const char*)(vh + (size_t)j * UU + d0) + seg);
            cp16(bs + AV_V0L + so, (const char*)(vl + (size_t)j * UU + d0) + seg);
            cp16(bs + AV_V1H + so, (const char*)(vh + (size_t)j * UU + d0 + 64) + seg);
            cp16(bs + AV_V1L + so, (const char*)(vl + (size_t)j * UU + d0 + 64) + seg);
        }
        CP_COMMIT();
    };

    const int lsub = lane >> 3;
    const int lrow = lane & 7;
    const int a_ro = (lsub & 1) * 8;
    const int a_ko = (lsub >> 1) * 16;
    const int wm = (warp & 1) * 32;
    const int wn = (warp >> 1) * 32;     // 0,32,64,96 within 128-wide d-chunk
    const int sub  = wn >> 6;            // which 64-d subtile
    const int nloc = wn & 63;
    const int grp = lane >> 2;
    const int qd  = lane & 3;

    issue(0, 0, 0);

    for (int dc = 0; dc < 4; dc++) {
        float acc[2][4][4];
#pragma unroll
        for (int mt = 0; mt < 2; mt++)
#pragma unroll
            for (int nt = 0; nt < 4; nt++)
#pragma unroll
                for (int i = 0; i < 4; i++) acc[mt][nt][i] = 0.f;

        for (int kc = 0; kc < 5; kc++) {
            const int it = dc * 5 + kc;
            if (it < 19) {
                const int nit = it + 1;
                issue(nit / 5, nit % 5, nit & 1);
                CP_WAIT(1);
            } else {
                CP_WAIT(0);
            }
            __syncthreads();

            const uint32_t bs = sbase + (it & 1) * AV_BUF;
            const uint32_t Vh = bs + AV_V0H + sub * 16384;
            const uint32_t Vl = Vh + 8192;

#pragma unroll
            for (int ks = 0; ks < 4; ks++) {
                uint32_t ah[2][4], al[2][4];
#pragma unroll
                for (int mt = 0; mt < 2; mt++) {
                    const uint32_t off = SWZ((wm + mt * 16 + lrow + a_ro) * 128 + ks * 32 + a_ko);
                    ldm_x4(ah[mt], bs + AV_PH + off);
                    ldm_x4(al[mt], bs + AV_PL + off);
                }
#pragma unroll
                for (int ntp = 0; ntp < 2; ntp++) {
                    const uint32_t off = SWZ((ks * 16 + (lsub & 1) * 8 + lrow) * 128
                                             + (nloc + ntp * 16 + (lsub >> 1) * 8) * 2);
                    uint32_t bh[4], bl[4];
                    ldm_x4t(bh, Vh + off);
                    ldm_x4t(bl, Vl + off);
#pragma unroll
                    for (int t = 0; t < 2; t++) {
#pragma unroll
                        for (int mt = 0; mt < 2; mt++) {
                            mma_bf16(acc[mt][ntp * 2 + t], ah[mt], bh + t * 2);
                            mma_bf16(acc[mt][ntp * 2 + t], ah[mt], bl + t * 2);
                            mma_bf16(acc[mt][ntp * 2 + t], al[mt], bh + t * 2);
                        }
                    }
                }
            }
            __syncthreads();
        }

        // write this d-chunk
#pragma unroll
        for (int mt = 0; mt < 2; mt++) {
            const int r0 = q0 + wm + mt * 16 + grp;
#pragma unroll
            for (int nt = 0; nt < 4; nt++) {
                const int col = dc * 128 + wn + nt * 8 + qd * 2;
                *(float2*)&out[((size_t)b * SS + r0) * UU + col] =
                    make_float2(acc[mt][nt][0], acc[mt][nt][1]);
                *(float2*)&out[((size_t)b * SS + r0 + 8) * UU + col] =
                    make_float2(acc[mt][nt][2], acc[mt][nt][3]);
            }
        }
    }
}

// ---------------------------------------------------------------------------
extern "C" void kernel_launch(void* const* d_in, const int* in_sizes, int n_in,
                              void* d_out, int out_size)
{
    const float* x  = (const float*)d_in[0];
    const float* Wq = (const float*)d_in[1];
    const float* Wk = (const float*)d_in[2];
    const float* Wv = (const float*)d_in[3];
    const float* bq = (const float*)d_in[4];
    const float* bk = (const float*)d_in[5];
    const float* bv = (const float*)d_in[6];
    float* out = (float*)d_out;

    cudaFuncSetAttribute(qkv_tc,
                         cudaFuncAttributeMaxDynamicSharedMemorySize, GEMM_SMEM);
    cudaFuncSetAttribute(scores_mma,
                         cudaFuncAttributeMaxDynamicSharedMemorySize, SC_SMEM);
    cudaFuncSetAttribute(av_mma,
                         cudaFuncAttributeMaxDynamicSharedMemorySize, AV_SMEM);

    prep_x<<<(BB * SS * DD / 4) / 256, 256>>>(x);
    prep_w<<<dim3(UU / 32, DD / 32, 3), 256>>>(Wq, Wk, Wv);
    qkv_tc<<<dim3(UU / 128, BB * SS / 128, 3), 256, GEMM_SMEM>>>(bq, bk, bv);
    scores_mma<<<dim3(NT2, BB), 256, SC_SMEM>>>();
    av_mma<<<dim3(NT2, BB), 256, AV_SMEM>>>(out);
}